// round 4
// baseline (speedup 1.0000x reference)
#include <cuda_runtime.h>
#include <math.h>

// Problem dims (fixed by the reference)
#define B_   4
#define S_   2048
#define E_   512
#define H_   8
#define DH_  64
#define FF2  2048
#define M_   8192   // B_*S_

// ---------------------------------------------------------------------------
// Scratch buffers (device globals -- no allocations allowed)
// ---------------------------------------------------------------------------
static __device__ float g_n  [(size_t)M_ * E_];   // norm1 output
static __device__ float g_q  [(size_t)M_ * E_];   // [B,H,S,DH]
static __device__ float g_k  [(size_t)M_ * E_];
static __device__ float g_v  [(size_t)M_ * E_];
static __device__ float g_ctx[(size_t)M_ * E_];   // [B,S,E]
static __device__ float g_x1 [(size_t)M_ * E_];   // residual-1 output
static __device__ float g_n2 [(size_t)M_ * E_];   // norm2 output
static __device__ float g_h  [(size_t)M_ * FF2];  // FFN hidden

// ---------------------------------------------------------------------------
// LayerNorm: mean + unbiased std (ddof=1), eps added to std.
//   which==0 : in = xext (d_in[0]),  out = g_n
//   which==1 : in = g_x1,            out = g_n2
// one block per row, 128 threads, E_=512 -> one float4 per thread
// ---------------------------------------------------------------------------
__global__ void ln_kernel(const float* __restrict__ xext,
                          const float* __restrict__ alpha,
                          const float* __restrict__ beta, int which)
{
    const float* x = (which == 0) ? xext : g_x1;
    float* out     = (which == 0) ? g_n  : g_n2;
    int row = blockIdx.x;
    int t   = threadIdx.x;
    float4 v = ((const float4*)(x + (size_t)row * E_))[t];
    float s  = v.x + v.y + v.z + v.w;
    float sq = v.x*v.x + v.y*v.y + v.z*v.z + v.w*v.w;
    #pragma unroll
    for (int o = 16; o; o >>= 1) {
        s  += __shfl_xor_sync(0xffffffffu, s,  o);
        sq += __shfl_xor_sync(0xffffffffu, sq, o);
    }
    __shared__ float ss[4], sqs[4];
    int w = t >> 5;
    if ((t & 31) == 0) { ss[w] = s; sqs[w] = sq; }
    __syncthreads();
    s  = ss[0] + ss[1] + ss[2] + ss[3];
    sq = sqs[0] + sqs[1] + sqs[2] + sqs[3];
    float mean = s * (1.0f / E_);
    float var  = fmaxf((sq - (float)E_ * mean * mean) * (1.0f / (E_ - 1)), 0.0f);
    float scal = alpha[0] / (sqrtf(var) + 1e-6f);
    float b    = beta[0];
    float4 o;
    o.x = (v.x - mean) * scal + b;
    o.y = (v.y - mean) * scal + b;
    o.z = (v.z - mean) * scal + b;
    o.w = (v.w - mean) * scal + b;
    ((float4*)(out + (size_t)row * E_))[t] = o;
}

// ---------------------------------------------------------------------------
// Epilogue functors for the generic SGEMM (store 4 consecutive n per call)
// ---------------------------------------------------------------------------
struct EpiQKV {                 // store into g_q/g_k/g_v in [B,H,S,DH] layout
    int sel; const float* bias;
    __device__ __forceinline__ void operator()(int m, int n, const float* v) const {
        float* out = (sel == 0) ? g_q : (sel == 1) ? g_k : g_v;
        int b = m >> 11, s = m & (S_ - 1);
        int h = n >> 6,  d = n & 63;
        float4 o = make_float4(v[0] + bias[n],     v[1] + bias[n + 1],
                               v[2] + bias[n + 2], v[3] + bias[n + 3]);
        *(float4*)(out + ((((size_t)b * H_ + h) * S_ + s) * DH_ + d)) = o;
    }
};
struct EpiOProj {               // g_x1 = x + ctx@wo + bo
    const float* bias; const float* resid;
    __device__ __forceinline__ void operator()(int m, int n, const float* v) const {
        size_t idx = (size_t)m * E_ + n;
        float4 r = *(const float4*)(resid + idx);
        float4 o = make_float4(v[0] + bias[n]     + r.x, v[1] + bias[n + 1] + r.y,
                               v[2] + bias[n + 2] + r.z, v[3] + bias[n + 3] + r.w);
        *(float4*)(g_x1 + idx) = o;
    }
};
struct EpiRelu {                // g_h = relu(n2@w1 + b1)
    const float* bias;
    __device__ __forceinline__ void operator()(int m, int n, const float* v) const {
        size_t idx = (size_t)m * FF2 + n;
        float4 o = make_float4(fmaxf(v[0] + bias[n],     0.f),
                               fmaxf(v[1] + bias[n + 1], 0.f),
                               fmaxf(v[2] + bias[n + 2], 0.f),
                               fmaxf(v[3] + bias[n + 3], 0.f));
        *(float4*)(g_h + idx) = o;
    }
};
struct EpiFinal {               // out = x1 + h@w2 + b2
    float* out; const float* bias;
    __device__ __forceinline__ void operator()(int m, int n, const float* v) const {
        size_t idx = (size_t)m * E_ + n;
        float4 r = *(const float4*)(g_x1 + idx);
        float4 o = make_float4(v[0] + bias[n]     + r.x, v[1] + bias[n + 1] + r.y,
                               v[2] + bias[n + 2] + r.z, v[3] + bias[n + 3] + r.w);
        *(float4*)(out + idx) = o;
    }
};

// ---------------------------------------------------------------------------
// Generic SGEMM: C[M,N] = A[M,K] @ B[K,N] (+ epilogue)
// BM=128, BN=128, BK=16, 256 threads, 8x8 register micro-tile.
// A selected from device globals by asel (0:g_n 1:g_ctx 2:g_n2 3:g_h).
// All dims divide tile sizes exactly (checked by construction).
// ---------------------------------------------------------------------------
template <class Epi>
__global__ void __launch_bounds__(256)
sgemm_kernel(int asel, const float* __restrict__ Bw, int K, int N, Epi epi)
{
    const float* A = (asel == 0) ? g_n : (asel == 1) ? g_ctx
                   : (asel == 2) ? g_n2 : g_h;
    const int BM = 128, BN = 128, BK = 16;
    __shared__ float As[BK][BM];   // A stored transposed: As[k][m]
    __shared__ float Bs[BK][BN];
    int m0  = blockIdx.y * BM;
    int n0  = blockIdx.x * BN;
    int tid = threadIdx.x;
    int tr  = tid >> 4, tc = tid & 15;

    float acc[8][8];
    #pragma unroll
    for (int i = 0; i < 8; i++)
        #pragma unroll
        for (int j = 0; j < 8; j++) acc[i][j] = 0.f;

    for (int k0 = 0; k0 < K; k0 += BK) {
        // load A tile (128x16), store transposed
        #pragma unroll
        for (int i = 0; i < 2; i++) {
            int idx = tid + i * 256;        // float4 index, 512 total
            int r   = idx >> 2;             // row in tile  (BK/4 = 4 groups/row)
            int cg  = idx & 3;
            float4 av = *(const float4*)(A + (size_t)(m0 + r) * K + k0 + cg * 4);
            As[cg * 4 + 0][r] = av.x;
            As[cg * 4 + 1][r] = av.y;
            As[cg * 4 + 2][r] = av.z;
            As[cg * 4 + 3][r] = av.w;
        }
        // load B tile (16x128)
        #pragma unroll
        for (int i = 0; i < 2; i++) {
            int idx = tid + i * 256;
            int r   = idx >> 5;             // BN/4 = 32 groups/row
            int cg  = idx & 31;
            *(float4*)&Bs[r][cg * 4] =
                *(const float4*)(Bw + (size_t)(k0 + r) * N + n0 + cg * 4);
        }
        __syncthreads();
        #pragma unroll
        for (int kk = 0; kk < BK; kk++) {
            float af[8], bf[8];
            *(float4*)&af[0] = *(const float4*)&As[kk][tr * 8];
            *(float4*)&af[4] = *(const float4*)&As[kk][tr * 8 + 4];
            *(float4*)&bf[0] = *(const float4*)&Bs[kk][tc * 8];
            *(float4*)&bf[4] = *(const float4*)&Bs[kk][tc * 8 + 4];
            #pragma unroll
            for (int i = 0; i < 8; i++)
                #pragma unroll
                for (int j = 0; j < 8; j++)
                    acc[i][j] = fmaf(af[i], bf[j], acc[i][j]);
        }
        __syncthreads();
    }
    #pragma unroll
    for (int i = 0; i < 8; i++) {
        int m = m0 + tr * 8 + i;
        epi(m, n0 + tc * 8,     &acc[i][0]);
        epi(m, n0 + tc * 8 + 4, &acc[i][4]);
    }
}

// ---------------------------------------------------------------------------
// Flash attention, fp32. One CTA = 64 queries of one (b,h). 128 threads.
// Thread (tr=tid/8, tc=tid%8) owns a 4x8 micro-tile of the 64x64 score/O tile.
// smem: Qst[d][r] (Q^T, pre-scaled), KPs (K^T, then reused for P), Vs[j][c].
// Exactly 48 KB static shared.
// ---------------------------------------------------------------------------
__global__ void __launch_bounds__(128)
attn_kernel(const int* __restrict__ mask)
{
    __shared__ float Qst[64][64];   // [d][r]
    __shared__ float KPs[64][64];   // K^T [d][j], then P [r][j]
    __shared__ float Vs [64][64];   // [j][c]

    int bh = blockIdx.y;
    int q0 = blockIdx.x * 64;
    int bb = bh >> 3;               // batch
    const float* Qb = g_q + (size_t)bh * S_ * DH_;
    const float* Kb = g_k + (size_t)bh * S_ * DH_;
    const float* Vb = g_v + (size_t)bh * S_ * DH_;
    const int*  mrow = mask + bb * S_;

    int tid = threadIdx.x;
    int tr  = tid >> 3, tc = tid & 7;

    // load + transpose + pre-scale Q
    #pragma unroll
    for (int i = 0; i < 8; i++) {
        int idx = tid + i * 128;    // float4 index, 1024 total
        int r   = idx >> 4, dg = idx & 15;
        float4 qv = *(const float4*)(Qb + (size_t)(q0 + r) * DH_ + dg * 4);
        const float sc = 0.125f;    // 1/sqrt(DH)
        Qst[dg * 4 + 0][r] = qv.x * sc;
        Qst[dg * 4 + 1][r] = qv.y * sc;
        Qst[dg * 4 + 2][r] = qv.z * sc;
        Qst[dg * 4 + 3][r] = qv.w * sc;
    }

    float acc[4][8];
    #pragma unroll
    for (int i = 0; i < 4; i++)
        #pragma unroll
        for (int c = 0; c < 8; c++) acc[i][c] = 0.f;
    float mi[4], li[4];
    #pragma unroll
    for (int i = 0; i < 4; i++) { mi[i] = -INFINITY; li[i] = 0.f; }

    for (int kt = 0; kt < S_; kt += 64) {
        // load K^T and V tiles
        #pragma unroll
        for (int i = 0; i < 8; i++) {
            int idx = tid + i * 128;
            int j   = idx >> 4, dg = idx & 15;
            float4 kv = *(const float4*)(Kb + (size_t)(kt + j) * DH_ + dg * 4);
            KPs[dg * 4 + 0][j] = kv.x;
            KPs[dg * 4 + 1][j] = kv.y;
            KPs[dg * 4 + 2][j] = kv.z;
            KPs[dg * 4 + 3][j] = kv.w;
            *(float4*)&Vs[j][dg * 4] =
                *(const float4*)(Vb + (size_t)(kt + j) * DH_ + dg * 4);
        }
        __syncthreads();

        // S = Q @ K^T  (inner dim d)
        float s[4][8];
        #pragma unroll
        for (int i = 0; i < 4; i++)
            #pragma unroll
            for (int j = 0; j < 8; j++) s[i][j] = 0.f;
        #pragma unroll 16
        for (int d = 0; d < 64; d++) {
            float a[4], b[8];
            *(float4*)a     = *(const float4*)&Qst[d][tr * 4];
            *(float4*)&b[0] = *(const float4*)&KPs[d][tc * 8];
            *(float4*)&b[4] = *(const float4*)&KPs[d][tc * 8 + 4];
            #pragma unroll
            for (int i = 0; i < 4; i++)
                #pragma unroll
                for (int j = 0; j < 8; j++)
                    s[i][j] = fmaf(a[i], b[j], s[i][j]);
        }
        __syncthreads();            // everyone done reading K^T

        // mask (key-wise)
        int4 mA = *(const int4*)(mrow + kt + tc * 8);
        int4 mB = *(const int4*)(mrow + kt + tc * 8 + 4);
        int mk[8] = { mA.x, mA.y, mA.z, mA.w, mB.x, mB.y, mB.z, mB.w };
        #pragma unroll
        for (int j = 0; j < 8; j++)
            if (mk[j] == 0) {
                #pragma unroll
                for (int i = 0; i < 4; i++) s[i][j] = -1e9f;
            }

        // online softmax (row stats replicated across the 8 threads of a row)
        #pragma unroll
        for (int i = 0; i < 4; i++) {
            float rm = s[i][0];
            #pragma unroll
            for (int j = 1; j < 8; j++) rm = fmaxf(rm, s[i][j]);
            rm = fmaxf(rm, __shfl_xor_sync(0xffffffffu, rm, 1));
            rm = fmaxf(rm, __shfl_xor_sync(0xffffffffu, rm, 2));
            rm = fmaxf(rm, __shfl_xor_sync(0xffffffffu, rm, 4));
            float mnew = fmaxf(mi[i], rm);
            float corr = __expf(mi[i] - mnew);
            mi[i] = mnew;
            float rs = 0.f;
            #pragma unroll
            for (int j = 0; j < 8; j++) {
                s[i][j] = __expf(s[i][j] - mnew);
                rs += s[i][j];
            }
            rs += __shfl_xor_sync(0xffffffffu, rs, 1);
            rs += __shfl_xor_sync(0xffffffffu, rs, 2);
            rs += __shfl_xor_sync(0xffffffffu, rs, 4);
            li[i] = li[i] * corr + rs;
            #pragma unroll
            for (int c = 0; c < 8; c++) acc[i][c] *= corr;
        }

        // write P (natural [r][j]) into KPs
        #pragma unroll
        for (int i = 0; i < 4; i++) {
            *(float4*)&KPs[tr * 4 + i][tc * 8]     = *(float4*)&s[i][0];
            *(float4*)&KPs[tr * 4 + i][tc * 8 + 4] = *(float4*)&s[i][4];
        }
        __syncthreads();

        // O += P @ V  (inner dim j)
        #pragma unroll 16
        for (int j = 0; j < 64; j++) {
            float b[8];
            *(float4*)&b[0] = *(const float4*)&Vs[j][tc * 8];
            *(float4*)&b[4] = *(const float4*)&Vs[j][tc * 8 + 4];
            float a[4];
            a[0] = KPs[tr * 4 + 0][j];
            a[1] = KPs[tr * 4 + 1][j];
            a[2] = KPs[tr * 4 + 2][j];
            a[3] = KPs[tr * 4 + 3][j];
            #pragma unroll
            for (int i = 0; i < 4; i++)
                #pragma unroll
                for (int c = 0; c < 8; c++)
                    acc[i][c] = fmaf(a[i], b[c], acc[i][c]);
        }
        __syncthreads();
    }

    // finalize: divide by l, write ctx back in [B,S,E] layout
    int hh = bh & 7;
    #pragma unroll
    for (int i = 0; i < 4; i++) {
        float inv = 1.0f / li[i];
        int srow = q0 + tr * 4 + i;
        float* orow = g_ctx + ((size_t)bb * S_ + srow) * E_ + hh * DH_ + tc * 8;
        float4 o0 = make_float4(acc[i][0] * inv, acc[i][1] * inv,
                                acc[i][2] * inv, acc[i][3] * inv);
        float4 o1 = make_float4(acc[i][4] * inv, acc[i][5] * inv,
                                acc[i][6] * inv, acc[i][7] * inv);
        *(float4*)orow       = o0;
        *(float4*)(orow + 4) = o1;
    }
}

// ---------------------------------------------------------------------------
// kernel_launch: 9 kernels on the default stream (graph-capturable, no allocs)
// ---------------------------------------------------------------------------
extern "C" void kernel_launch(void* const* d_in, const int* in_sizes, int n_in,
                              void* d_out, int out_size)
{
    const float* x    = (const float*)d_in[0];
    const int*   mask = (const int*)  d_in[1];
    const float* wq   = (const float*)d_in[2];
    const float* bq   = (const float*)d_in[3];
    const float* wk   = (const float*)d_in[4];
    const float* bk   = (const float*)d_in[5];
    const float* wv   = (const float*)d_in[6];
    const float* bv   = (const float*)d_in[7];
    const float* wo   = (const float*)d_in[8];
    const float* bo   = (const float*)d_in[9];
    const float* w1   = (const float*)d_in[10];
    const float* b1   = (const float*)d_in[11];
    const float* w2   = (const float*)d_in[12];
    const float* b2   = (const float*)d_in[13];
    const float* al1  = (const float*)d_in[14];
    const float* be1  = (const float*)d_in[15];
    const float* al2  = (const float*)d_in[16];
    const float* be2  = (const float*)d_in[17];
    float* out = (float*)d_out;

    // norm1
    ln_kernel<<<M_, 128>>>(x, al1, be1, 0);

    // Q/K/V projections (N=512, K=512)
    dim3 g512(E_ / 128, M_ / 128);          // (4, 64)
    sgemm_kernel<EpiQKV><<<g512, 256>>>(0, wq, E_, E_, EpiQKV{0, bq});
    sgemm_kernel<EpiQKV><<<g512, 256>>>(0, wk, E_, E_, EpiQKV{1, bk});
    sgemm_kernel<EpiQKV><<<g512, 256>>>(0, wv, E_, E_, EpiQKV{2, bv});

    // attention
    dim3 ga(S_ / 64, B_ * H_);              // (32, 32)
    attn_kernel<<<ga, 128>>>(mask);

    // O projection + residual 1
    sgemm_kernel<EpiOProj><<<g512, 256>>>(1, wo, E_, E_, EpiOProj{bo, x});

    // norm2
    ln_kernel<<<M_, 128>>>(nullptr, al2, be2, 1);

    // FFN1 (N=2048) with ReLU
    dim3 gff1(FF2 / 128, M_ / 128);         // (16, 64)
    sgemm_kernel<EpiRelu><<<gff1, 256>>>(2, w1, E_, FF2, EpiRelu{b1});

    // FFN2 (K=2048) + residual 2 -> final output
    sgemm_kernel<EpiFinal><<<g512, 256>>>(3, w2, FF2, E_, EpiFinal{out, b2});
}

// round 6
// speedup vs baseline: 3.5317x; 3.5317x over previous
#include <cuda_runtime.h>
#include <math.h>
#include <stdint.h>

// Problem dims (fixed by the reference)
#define B_   4
#define S_   2048
#define E_   512
#define H_   8
#define DH_  64
#define FF2  2048
#define M_   8192   // B_*S_

// ---------------------------------------------------------------------------
// Scratch buffers (device globals -- no allocations allowed)
// ---------------------------------------------------------------------------
static __device__ float g_n  [(size_t)M_ * E_];   // norm1 output
static __device__ float g_q  [(size_t)M_ * E_];   // [B,H,S,DH]
static __device__ float g_k  [(size_t)M_ * E_];
static __device__ float g_v  [(size_t)M_ * E_];
static __device__ float g_ctx[(size_t)M_ * E_];   // [B,S,E]
static __device__ float g_x1 [(size_t)M_ * E_];   // residual-1 output
static __device__ float g_n2 [(size_t)M_ * E_];   // norm2 output
static __device__ float g_h  [(size_t)M_ * FF2];  // FFN hidden

// ---------------------------------------------------------------------------
// tf32 helpers
// ---------------------------------------------------------------------------
__device__ __forceinline__ float f2tf(float x) {
    uint32_t r;
    asm("cvt.rna.tf32.f32 %0, %1;" : "=r"(r) : "f"(x));
    return __uint_as_float(r);
}
__device__ __forceinline__ void mma_tf32(float c[4],
                                         uint32_t a0, uint32_t a1,
                                         uint32_t a2, uint32_t a3,
                                         uint32_t b0, uint32_t b1)
{
    asm volatile(
        "mma.sync.aligned.m16n8k8.row.col.f32.tf32.tf32.f32 "
        "{%0,%1,%2,%3}, {%4,%5,%6,%7}, {%8,%9}, {%0,%1,%2,%3};"
        : "+f"(c[0]), "+f"(c[1]), "+f"(c[2]), "+f"(c[3])
        : "r"(a0), "r"(a1), "r"(a2), "r"(a3), "r"(b0), "r"(b1));
}
#define FBITS(x) __float_as_uint(x)

// ---------------------------------------------------------------------------
// LayerNorm: mean + unbiased std (ddof=1), eps added to std.
// ---------------------------------------------------------------------------
__global__ void ln_kernel(const float* __restrict__ xext,
                          const float* __restrict__ alpha,
                          const float* __restrict__ beta, int which)
{
    const float* x = (which == 0) ? xext : g_x1;
    float* out     = (which == 0) ? g_n  : g_n2;
    int row = blockIdx.x;
    int t   = threadIdx.x;
    float4 v = ((const float4*)(x + (size_t)row * E_))[t];
    float s  = v.x + v.y + v.z + v.w;
    float sq = v.x*v.x + v.y*v.y + v.z*v.z + v.w*v.w;
    #pragma unroll
    for (int o = 16; o; o >>= 1) {
        s  += __shfl_xor_sync(0xffffffffu, s,  o);
        sq += __shfl_xor_sync(0xffffffffu, sq, o);
    }
    __shared__ float ss[4], sqs[4];
    int w = t >> 5;
    if ((t & 31) == 0) { ss[w] = s; sqs[w] = sq; }
    __syncthreads();
    s  = ss[0] + ss[1] + ss[2] + ss[3];
    sq = sqs[0] + sqs[1] + sqs[2] + sqs[3];
    float mean = s * (1.0f / E_);
    float var  = fmaxf((sq - (float)E_ * mean * mean) * (1.0f / (E_ - 1)), 0.0f);
    float scal = alpha[0] / (sqrtf(var) + 1e-6f);
    float b    = beta[0];
    float4 o;
    o.x = (v.x - mean) * scal + b;
    o.y = (v.y - mean) * scal + b;
    o.z = (v.z - mean) * scal + b;
    o.w = (v.w - mean) * scal + b;
    ((float4*)(out + (size_t)row * E_))[t] = o;
}

// ---------------------------------------------------------------------------
// Epilogue functors: receive (m, n, v0, v1) = two adjacent-n fp32 results
// ---------------------------------------------------------------------------
struct EpiQKV {                 // store into g_q/g_k/g_v in [B,H,S,DH] layout
    int sel; const float* bias;
    __device__ __forceinline__ void operator()(int m, int n, float v0, float v1) const {
        float* out = (sel == 0) ? g_q : (sel == 1) ? g_k : g_v;
        int b = m >> 11, s = m & (S_ - 1);
        int h = n >> 6,  d = n & 63;
        float2 o = make_float2(v0 + bias[n], v1 + bias[n + 1]);
        *(float2*)(out + ((((size_t)b * H_ + h) * S_ + s) * DH_ + d)) = o;
    }
};
struct EpiOProj {               // g_x1 = x + ctx@wo + bo
    const float* bias; const float* resid;
    __device__ __forceinline__ void operator()(int m, int n, float v0, float v1) const {
        size_t idx = (size_t)m * E_ + n;
        float2 r = *(const float2*)(resid + idx);
        *(float2*)(g_x1 + idx) =
            make_float2(v0 + bias[n] + r.x, v1 + bias[n + 1] + r.y);
    }
};
struct EpiRelu {                // g_h = relu(n2@w1 + b1)
    const float* bias;
    __device__ __forceinline__ void operator()(int m, int n, float v0, float v1) const {
        size_t idx = (size_t)m * FF2 + n;
        *(float2*)(g_h + idx) =
            make_float2(fmaxf(v0 + bias[n], 0.f), fmaxf(v1 + bias[n + 1], 0.f));
    }
};
struct EpiFinal {               // out = x1 + h@w2 + b2
    float* out; const float* bias;
    __device__ __forceinline__ void operator()(int m, int n, float v0, float v1) const {
        size_t idx = (size_t)m * E_ + n;
        float2 r = *(const float2*)(g_x1 + idx);
        *(float2*)(out + idx) =
            make_float2(v0 + bias[n] + r.x, v1 + bias[n + 1] + r.y);
    }
};

// ---------------------------------------------------------------------------
// tf32 tensor-core GEMM: C[M,N] = A[M,K] @ B[K,N] (+ epilogue)
// CTA tile 128x128, BK=32, 256 threads = 8 warps (4 in m x 2 in n).
// Warp tile 32x64 -> 2 m16 x 8 n8 mma tiles.
// Smem pads: As stride 36 (=4 mod 32), Bs stride 136 (=8 mod 32): fragment
// gathers are bank-conflict-free (A: bank=4g+t; B: bank=8t+g).
// ---------------------------------------------------------------------------
template <class Epi>
__global__ void __launch_bounds__(256, 2)
gemm_tf32(int asel, const float* __restrict__ Bw, int K, int N, Epi epi)
{
    const float* A = (asel == 0) ? g_n : (asel == 1) ? g_ctx
                   : (asel == 2) ? g_n2 : g_h;
    __shared__ float As[128][36];
    __shared__ float Bs[32][136];

    int tid  = threadIdx.x;
    int wid  = tid >> 5, lane = tid & 31;
    int g    = lane >> 2, t = lane & 3;
    int wm   = wid & 3,  wn = wid >> 2;      // warp grid 4x2
    int m0   = blockIdx.y * 128;
    int n0   = blockIdx.x * 128;

    float acc[2][8][4];
    #pragma unroll
    for (int mt = 0; mt < 2; mt++)
        #pragma unroll
        for (int nt = 0; nt < 8; nt++)
            #pragma unroll
            for (int i = 0; i < 4; i++) acc[mt][nt][i] = 0.f;

    for (int k0 = 0; k0 < K; k0 += 32) {
        // A tile 128x32 : 1024 float4, 4 per thread
        #pragma unroll
        for (int i = 0; i < 4; i++) {
            int idx = tid + i * 256;
            int r   = idx >> 3;
            int c   = (idx & 7) * 4;
            float4 v = *(const float4*)(A + (size_t)(m0 + r) * K + k0 + c);
            float4 o = make_float4(f2tf(v.x), f2tf(v.y), f2tf(v.z), f2tf(v.w));
            *(float4*)&As[r][c] = o;
        }
        // B tile 32x128 : 1024 float4, 4 per thread
        #pragma unroll
        for (int i = 0; i < 4; i++) {
            int idx = tid + i * 256;
            int r   = idx >> 5;
            int c   = (idx & 31) * 4;
            float4 v = *(const float4*)(Bw + (size_t)(k0 + r) * N + n0 + c);
            float4 o = make_float4(f2tf(v.x), f2tf(v.y), f2tf(v.z), f2tf(v.w));
            *(float4*)&Bs[r][c] = o;
        }
        __syncthreads();

        #pragma unroll
        for (int ks = 0; ks < 4; ks++) {
            int kk = ks * 8;
            uint32_t a[2][4];
            #pragma unroll
            for (int mt = 0; mt < 2; mt++) {
                int rb = wm * 32 + mt * 16;
                a[mt][0] = FBITS(As[rb + g    ][kk + t    ]);
                a[mt][1] = FBITS(As[rb + g + 8][kk + t    ]);
                a[mt][2] = FBITS(As[rb + g    ][kk + t + 4]);
                a[mt][3] = FBITS(As[rb + g + 8][kk + t + 4]);
            }
            #pragma unroll
            for (int nt = 0; nt < 8; nt++) {
                int nb = wn * 64 + nt * 8;
                uint32_t b0 = FBITS(Bs[kk + t    ][nb + g]);
                uint32_t b1 = FBITS(Bs[kk + t + 4][nb + g]);
                mma_tf32(acc[0][nt], a[0][0], a[0][1], a[0][2], a[0][3], b0, b1);
                mma_tf32(acc[1][nt], a[1][0], a[1][1], a[1][2], a[1][3], b0, b1);
            }
        }
        __syncthreads();
    }

    #pragma unroll
    for (int mt = 0; mt < 2; mt++) {
        int rb = m0 + wm * 32 + mt * 16;
        #pragma unroll
        for (int nt = 0; nt < 8; nt++) {
            int n = n0 + wn * 64 + nt * 8 + 2 * t;
            epi(rb + g,     n, acc[mt][nt][0], acc[mt][nt][1]);
            epi(rb + g + 8, n, acc[mt][nt][2], acc[mt][nt][3]);
        }
    }
}

// ---------------------------------------------------------------------------
// Flash attention with tf32 mma. One CTA = 64 queries of one (b,h).
// 128 threads = 4 warps; warp w owns q rows [16w, 16w+16).
// Q fragments are register-resident for all kt iterations; KP smem buffer
// stages Q, then holds K^T-source tile, then P. Vs holds V.
// Pads: KP stride 68 (=4 mod 32), Vs stride 72 (=8 mod 32) -> conflict-free.
// ---------------------------------------------------------------------------
__global__ void __launch_bounds__(128)
attn_tf32(const int* __restrict__ mask)
{
    __shared__ float KP[64][68];
    __shared__ float Vs[64][72];

    int tid  = threadIdx.x;
    int wid  = tid >> 5, lane = tid & 31;
    int g    = lane >> 2, t = lane & 3;
    int qb   = wid * 16;

    int bh = blockIdx.y;
    int q0 = blockIdx.x * 64;
    int bb = bh >> 3, hh = bh & 7;
    const float* Qb = g_q + (size_t)bh * S_ * DH_;
    const float* Kb = g_k + (size_t)bh * S_ * DH_;
    const float* Vb = g_v + (size_t)bh * S_ * DH_;
    const int* mrow = mask + bb * S_;

    // stage Q (prescaled by 1/sqrt(DH), tf32-rounded)
    #pragma unroll
    for (int i = 0; i < 8; i++) {
        int idx = tid + i * 128;        // 1024 float4 total
        int r   = idx >> 4;
        int c   = (idx & 15) * 4;
        float4 v = *(const float4*)(Qb + (size_t)(q0 + r) * DH_ + c);
        const float sc = 0.125f;
        *(float4*)&KP[r][c] = make_float4(f2tf(v.x * sc), f2tf(v.y * sc),
                                          f2tf(v.z * sc), f2tf(v.w * sc));
    }
    __syncthreads();

    // Q fragments to registers (reused for every key tile)
    uint32_t qa[8][4];
    #pragma unroll
    for (int ks = 0; ks < 8; ks++) {
        int kk = ks * 8;
        qa[ks][0] = FBITS(KP[qb + g    ][kk + t    ]);
        qa[ks][1] = FBITS(KP[qb + g + 8][kk + t    ]);
        qa[ks][2] = FBITS(KP[qb + g    ][kk + t + 4]);
        qa[ks][3] = FBITS(KP[qb + g + 8][kk + t + 4]);
    }
    __syncthreads();

    float oacc[8][4];
    #pragma unroll
    for (int nt = 0; nt < 8; nt++)
        #pragma unroll
        for (int i = 0; i < 4; i++) oacc[nt][i] = 0.f;
    float mi[2] = { -INFINITY, -INFINITY };
    float li[2] = { 0.f, 0.f };

    for (int kt = 0; kt < S_; kt += 64) {
        // load K and V tiles (tf32-rounded)
        #pragma unroll
        for (int i = 0; i < 8; i++) {
            int idx = tid + i * 128;
            int r   = idx >> 4;
            int c   = (idx & 15) * 4;
            float4 kv = *(const float4*)(Kb + (size_t)(kt + r) * DH_ + c);
            *(float4*)&KP[r][c] = make_float4(f2tf(kv.x), f2tf(kv.y),
                                              f2tf(kv.z), f2tf(kv.w));
            float4 vv = *(const float4*)(Vb + (size_t)(kt + r) * DH_ + c);
            *(float4*)&Vs[r][c] = make_float4(f2tf(vv.x), f2tf(vv.y),
                                              f2tf(vv.z), f2tf(vv.w));
        }
        __syncthreads();

        // S = Qs @ K^T ; B frag [k=d][n=j] = K[j][d]
        float sacc[8][4];
        #pragma unroll
        for (int nt = 0; nt < 8; nt++)
            #pragma unroll
            for (int i = 0; i < 4; i++) sacc[nt][i] = 0.f;
        #pragma unroll
        for (int ks = 0; ks < 8; ks++) {
            int kk = ks * 8;
            #pragma unroll
            for (int nt = 0; nt < 8; nt++) {
                int jb = nt * 8;
                uint32_t b0 = FBITS(KP[jb + g][kk + t    ]);
                uint32_t b1 = FBITS(KP[jb + g][kk + t + 4]);
                mma_tf32(sacc[nt], qa[ks][0], qa[ks][1], qa[ks][2], qa[ks][3],
                         b0, b1);
            }
        }
        __syncthreads();    // done reading K tile

        // key-wise mask
        #pragma unroll
        for (int nt = 0; nt < 8; nt++) {
            int j = kt + nt * 8 + 2 * t;
            if (__ldg(mrow + j)     == 0) { sacc[nt][0] = -1e9f; sacc[nt][2] = -1e9f; }
            if (__ldg(mrow + j + 1) == 0) { sacc[nt][1] = -1e9f; sacc[nt][3] = -1e9f; }
        }

        // online softmax (rows g and g+8; stats shared across the 4 tig lanes)
        #pragma unroll
        for (int h = 0; h < 2; h++) {
            float rm = -INFINITY;
            #pragma unroll
            for (int nt = 0; nt < 8; nt++)
                rm = fmaxf(rm, fmaxf(sacc[nt][2*h], sacc[nt][2*h + 1]));
            rm = fmaxf(rm, __shfl_xor_sync(0xffffffffu, rm, 1));
            rm = fmaxf(rm, __shfl_xor_sync(0xffffffffu, rm, 2));
            float mnew = fmaxf(mi[h], rm);
            float corr = __expf(mi[h] - mnew);
            mi[h] = mnew;
            float rs = 0.f;
            #pragma unroll
            for (int nt = 0; nt < 8; nt++) {
                float e0 = __expf(sacc[nt][2*h]     - mnew);
                float e1 = __expf(sacc[nt][2*h + 1] - mnew);
                sacc[nt][2*h]     = e0;
                sacc[nt][2*h + 1] = e1;
                rs += e0 + e1;
            }
            rs += __shfl_xor_sync(0xffffffffu, rs, 1);
            rs += __shfl_xor_sync(0xffffffffu, rs, 2);
            li[h] = li[h] * corr + rs;
            #pragma unroll
            for (int nt = 0; nt < 8; nt++) {
                oacc[nt][2*h]     *= corr;
                oacc[nt][2*h + 1] *= corr;
            }
        }

        // write P (tf32-rounded) into KP
        #pragma unroll
        for (int nt = 0; nt < 8; nt++) {
            int jc = nt * 8 + 2 * t;
            *(float2*)&KP[qb + g    ][jc] =
                make_float2(f2tf(sacc[nt][0]), f2tf(sacc[nt][1]));
            *(float2*)&KP[qb + g + 8][jc] =
                make_float2(f2tf(sacc[nt][2]), f2tf(sacc[nt][3]));
        }
        __syncthreads();

        // O += P @ V ; A frag from KP (row-major), B frag [k=j][n=c] = V[j][c]
        #pragma unroll
        for (int js = 0; js < 8; js++) {
            int j0 = js * 8;
            uint32_t a0 = FBITS(KP[qb + g    ][j0 + t    ]);
            uint32_t a1 = FBITS(KP[qb + g + 8][j0 + t    ]);
            uint32_t a2 = FBITS(KP[qb + g    ][j0 + t + 4]);
            uint32_t a3 = FBITS(KP[qb + g + 8][j0 + t + 4]);
            #pragma unroll
            for (int nt = 0; nt < 8; nt++) {
                int db = nt * 8;
                uint32_t b0 = FBITS(Vs[j0 + t    ][db + g]);
                uint32_t b1 = FBITS(Vs[j0 + t + 4][db + g]);
                mma_tf32(oacc[nt], a0, a1, a2, a3, b0, b1);
            }
        }
        __syncthreads();    // before next iteration overwrites KP / Vs
    }

    // finalize: 1/l scale, write ctx in [B,S,E] layout
    #pragma unroll
    for (int h = 0; h < 2; h++) {
        float inv = 1.0f / li[h];
        int r = q0 + qb + g + 8 * h;
        float* orow = g_ctx + ((size_t)bb * S_ + r) * E_ + hh * DH_;
        #pragma unroll
        for (int nt = 0; nt < 8; nt++) {
            int d = nt * 8 + 2 * t;
            *(float2*)(orow + d) = make_float2(oacc[nt][2*h] * inv,
                                               oacc[nt][2*h + 1] * inv);
        }
    }
}

// ---------------------------------------------------------------------------
// kernel_launch: 9 kernels on the default stream (graph-capturable, no allocs)
// ---------------------------------------------------------------------------
extern "C" void kernel_launch(void* const* d_in, const int* in_sizes, int n_in,
                              void* d_out, int out_size)
{
    const float* x    = (const float*)d_in[0];
    const int*   mask = (const int*)  d_in[1];
    const float* wq   = (const float*)d_in[2];
    const float* bq   = (const float*)d_in[3];
    const float* wk   = (const float*)d_in[4];
    const float* bk   = (const float*)d_in[5];
    const float* wv   = (const float*)d_in[6];
    const float* bv   = (const float*)d_in[7];
    const float* wo   = (const float*)d_in[8];
    const float* bo   = (const float*)d_in[9];
    const float* w1   = (const float*)d_in[10];
    const float* b1   = (const float*)d_in[11];
    const float* w2   = (const float*)d_in[12];
    const float* b2   = (const float*)d_in[13];
    const float* al1  = (const float*)d_in[14];
    const float* be1  = (const float*)d_in[15];
    const float* al2  = (const float*)d_in[16];
    const float* be2  = (const float*)d_in[17];
    float* out = (float*)d_out;

    // norm1
    ln_kernel<<<M_, 128>>>(x, al1, be1, 0);

    // Q/K/V projections (N=512, K=512)
    dim3 g512(E_ / 128, M_ / 128);          // (4, 64)
    gemm_tf32<EpiQKV><<<g512, 256>>>(0, wq, E_, E_, EpiQKV{0, bq});
    gemm_tf32<EpiQKV><<<g512, 256>>>(0, wk, E_, E_, EpiQKV{1, bk});
    gemm_tf32<EpiQKV><<<g512, 256>>>(0, wv, E_, E_, EpiQKV{2, bv});

    // attention
    dim3 ga(S_ / 64, B_ * H_);              // (32, 32)
    attn_tf32<<<ga, 128>>>(mask);

    // O projection + residual 1
    gemm_tf32<EpiOProj><<<g512, 256>>>(1, wo, E_, E_, EpiOProj{bo, x});

    // norm2
    ln_kernel<<<M_, 128>>>(nullptr, al2, be2, 1);

    // FFN1 (N=2048) with ReLU
    dim3 gff1(FF2 / 128, M_ / 128);         // (16, 64)
    gemm_tf32<EpiRelu><<<gff1, 256>>>(2, w1, E_, FF2, EpiRelu{b1});

    // FFN2 (K=2048) + residual 2 -> final output
    gemm_tf32<EpiFinal><<<g512, 256>>>(3, w2, FF2, E_, EpiFinal{out, b2});
}

// round 8
// speedup vs baseline: 3.9357x; 1.1144x over previous
#include <cuda_runtime.h>
#include <math.h>
#include <stdint.h>

// Problem dims (fixed by the reference)
#define B_   4
#define S_   2048
#define E_   512
#define H_   8
#define DH_  64
#define FF2  2048
#define M_   8192   // B_*S_

// ---------------------------------------------------------------------------
// Scratch buffers (device globals -- no allocations allowed)
// ---------------------------------------------------------------------------
static __device__ float g_n  [(size_t)M_ * E_];   // norm1 output
static __device__ float g_q  [(size_t)M_ * E_];   // [B,H,S,DH]
static __device__ float g_k  [(size_t)M_ * E_];
static __device__ float g_v  [(size_t)M_ * E_];
static __device__ float g_ctx[(size_t)M_ * E_];   // [B,S,E]
static __device__ float g_x1 [(size_t)M_ * E_];   // residual-1 output
static __device__ float g_n2 [(size_t)M_ * E_];   // norm2 output
static __device__ float g_h  [(size_t)M_ * FF2];  // FFN hidden

// ---------------------------------------------------------------------------
// PTX helpers
// ---------------------------------------------------------------------------
__device__ __forceinline__ void mma_tf32(float c[4],
                                         uint32_t a0, uint32_t a1,
                                         uint32_t a2, uint32_t a3,
                                         uint32_t b0, uint32_t b1)
{
    asm volatile(
        "mma.sync.aligned.m16n8k8.row.col.f32.tf32.tf32.f32 "
        "{%0,%1,%2,%3}, {%4,%5,%6,%7}, {%8,%9}, {%0,%1,%2,%3};"
        : "+f"(c[0]), "+f"(c[1]), "+f"(c[2]), "+f"(c[3])
        : "r"(a0), "r"(a1), "r"(a2), "r"(a3), "r"(b0), "r"(b1));
}
__device__ __forceinline__ void cp_async16(void* smem, const void* gmem) {
    uint32_t s = (uint32_t)__cvta_generic_to_shared(smem);
    asm volatile("cp.async.cg.shared.global [%0], [%1], 16;" :: "r"(s), "l"(gmem));
}
#define CP_COMMIT()  asm volatile("cp.async.commit_group;" ::: "memory")
#define CP_WAIT1()   asm volatile("cp.async.wait_group 1;" ::: "memory")
// ldmatrix x4: 8 rows x 16B per matrix; 32-bit elements -> tf32 fragment layout
__device__ __forceinline__ void ldsm_x4(uint32_t r[4], const void* p) {
    uint32_t s = (uint32_t)__cvta_generic_to_shared(p);
    asm volatile("ldmatrix.sync.aligned.m8n8.x4.shared.b16 {%0,%1,%2,%3}, [%4];"
        : "=r"(r[0]), "=r"(r[1]), "=r"(r[2]), "=r"(r[3]) : "r"(s));
}
#define FBITS(x) __float_as_uint(x)

// ---------------------------------------------------------------------------
// LayerNorm: mean + unbiased std (ddof=1), eps added to std.
// ---------------------------------------------------------------------------
__global__ void ln_kernel(const float* __restrict__ xext,
                          const float* __restrict__ alpha,
                          const float* __restrict__ beta, int which)
{
    const float* x = (which == 0) ? xext : g_x1;
    float* out     = (which == 0) ? g_n  : g_n2;
    int row = blockIdx.x;
    int t   = threadIdx.x;
    float4 v = ((const float4*)(x + (size_t)row * E_))[t];
    float s  = v.x + v.y + v.z + v.w;
    float sq = v.x*v.x + v.y*v.y + v.z*v.z + v.w*v.w;
    #pragma unroll
    for (int o = 16; o; o >>= 1) {
        s  += __shfl_xor_sync(0xffffffffu, s,  o);
        sq += __shfl_xor_sync(0xffffffffu, sq, o);
    }
    __shared__ float ss[4], sqs[4];
    int w = t >> 5;
    if ((t & 31) == 0) { ss[w] = s; sqs[w] = sq; }
    __syncthreads();
    s  = ss[0] + ss[1] + ss[2] + ss[3];
    sq = sqs[0] + sqs[1] + sqs[2] + sqs[3];
    float mean = s * (1.0f / E_);
    float var  = fmaxf((sq - (float)E_ * mean * mean) * (1.0f / (E_ - 1)), 0.0f);
    float scal = alpha[0] / (sqrtf(var) + 1e-6f);
    float b    = beta[0];
    float4 o;
    o.x = (v.x - mean) * scal + b;
    o.y = (v.y - mean) * scal + b;
    o.z = (v.z - mean) * scal + b;
    o.w = (v.w - mean) * scal + b;
    ((float4*)(out + (size_t)row * E_))[t] = o;
}

// ---------------------------------------------------------------------------
// Epilogue functors: receive (m, n, v0, v1) = two adjacent-n fp32 results
// ---------------------------------------------------------------------------
struct EpiQKV3 {                // blockIdx.z selects q/k/v; [B,H,S,DH] layout
    const float *bq, *bk, *bv;
    __device__ __forceinline__ void operator()(int m, int n, float v0, float v1) const {
        int z = blockIdx.z;
        const float* bias = (z == 0) ? bq : (z == 1) ? bk : bv;
        float* out        = (z == 0) ? g_q : (z == 1) ? g_k : g_v;
        int b = m >> 11, s = m & (S_ - 1);
        int h = n >> 6,  d = n & 63;
        *(float2*)(out + ((((size_t)b * H_ + h) * S_ + s) * DH_ + d)) =
            make_float2(v0 + bias[n], v1 + bias[n + 1]);
    }
};
struct EpiOProj {               // g_x1 = x + ctx@wo + bo
    const float* bias; const float* resid;
    __device__ __forceinline__ void operator()(int m, int n, float v0, float v1) const {
        size_t idx = (size_t)m * E_ + n;
        float2 r = *(const float2*)(resid + idx);
        *(float2*)(g_x1 + idx) =
            make_float2(v0 + bias[n] + r.x, v1 + bias[n + 1] + r.y);
    }
};
struct EpiRelu {                // g_h = relu(n2@w1 + b1)
    const float* bias;
    __device__ __forceinline__ void operator()(int m, int n, float v0, float v1) const {
        size_t idx = (size_t)m * FF2 + n;
        *(float2*)(g_h + idx) =
            make_float2(fmaxf(v0 + bias[n], 0.f), fmaxf(v1 + bias[n + 1], 0.f));
    }
};
struct EpiFinal {               // out = x1 + h@w2 + b2
    float* out; const float* bias;
    __device__ __forceinline__ void operator()(int m, int n, float v0, float v1) const {
        size_t idx = (size_t)m * E_ + n;
        float2 r = *(const float2*)(g_x1 + idx);
        *(float2*)(out + idx) =
            make_float2(v0 + bias[n] + r.x, v1 + bias[n + 1] + r.y);
    }
};

// ---------------------------------------------------------------------------
// tf32 tensor-core GEMM: C[M,N] = A[M,K] @ B[K,N] (+ epilogue)
// CTA tile 128x128, BK=32, 256 threads = 8 warps (4m x 2n), warp tile 32x64.
// 2-stage cp.async double-buffered smem; A-fragments via ldmatrix.x4.
// Dynamic smem: As[2][128][36] + Bs[2][32][136]  (71680 B).
// As stride 36 (=4 mod 32): LDSM row addrs on distinct 4-bank groups.
// Bs stride 136 (=8 mod 32): scalar b-frag LDS conflict-free (bank=8t+g).
// ---------------------------------------------------------------------------
#define AS(b,r,c) As[(((b) << 7) + (r)) * 36 + (c)]
#define BS(b,r,c) Bs[(((b) << 5) + (r)) * 136 + (c)]
#define GEMM_SMEM_BYTES ((2*128*36 + 2*32*136) * 4)

template <class Epi>
__global__ void __launch_bounds__(256, 2)
gemm_tf32(int asel, const float* __restrict__ B0, const float* __restrict__ B1,
          const float* __restrict__ B2, int K, int N, Epi epi)
{
    const float* A = (asel == 0) ? g_n : (asel == 1) ? g_ctx
                   : (asel == 2) ? g_n2 : g_h;
    const float* Bw = (blockIdx.z == 0) ? B0 : (blockIdx.z == 1) ? B1 : B2;

    extern __shared__ float smem[];
    float* As = smem;
    float* Bs = smem + 2 * 128 * 36;

    int tid  = threadIdx.x;
    int wid  = tid >> 5, lane = tid & 31;
    int g    = lane >> 2, t = lane & 3;
    int rr   = lane & 7, qq = lane >> 3;
    int wm   = wid & 3,  wn = wid >> 2;      // warp grid 4x2
    int m0   = blockIdx.y * 128;
    int n0   = blockIdx.x * 128;

    // ldmatrix per-lane offsets (row perturbation / col half select)
    int lrow = rr + ((qq & 1) << 3);
    int lcol = (qq >> 1) << 2;

    auto load_stage = [&](int buf, int k0) {
        #pragma unroll
        for (int i = 0; i < 4; i++) {                 // A: 128x32 = 1024 f4
            int idx = tid + i * 256;
            int r = idx >> 3, c = (idx & 7) * 4;
            cp_async16(&AS(buf, r, c), A + (size_t)(m0 + r) * K + k0 + c);
        }
        #pragma unroll
        for (int i = 0; i < 4; i++) {                 // B: 32x128 = 1024 f4
            int idx = tid + i * 256;
            int r = idx >> 5, c = (idx & 31) * 4;
            cp_async16(&BS(buf, r, c), Bw + (size_t)(k0 + r) * N + n0 + c);
        }
    };

    float acc[2][8][4];
    #pragma unroll
    for (int mt = 0; mt < 2; mt++)
        #pragma unroll
        for (int nt = 0; nt < 8; nt++)
            #pragma unroll
            for (int i = 0; i < 4; i++) acc[mt][nt][i] = 0.f;

    load_stage(0, 0);
    CP_COMMIT();
    int buf = 0;

    for (int k0 = 0; k0 < K; k0 += 32) {
        if (k0 + 32 < K) load_stage(buf ^ 1, k0 + 32);
        CP_COMMIT();
        CP_WAIT1();
        __syncthreads();

        #pragma unroll
        for (int ks = 0; ks < 4; ks++) {
            int kk = ks * 8;
            uint32_t a[2][4];
            #pragma unroll
            for (int mt = 0; mt < 2; mt++)
                ldsm_x4(a[mt], &AS(buf, wm * 32 + mt * 16 + lrow, kk + lcol));
            #pragma unroll
            for (int nt = 0; nt < 8; nt++) {
                int nb = wn * 64 + nt * 8;
                uint32_t b0 = FBITS(BS(buf, kk + t,     nb + g));
                uint32_t b1 = FBITS(BS(buf, kk + t + 4, nb + g));
                mma_tf32(acc[0][nt], a[0][0], a[0][1], a[0][2], a[0][3], b0, b1);
                mma_tf32(acc[1][nt], a[1][0], a[1][1], a[1][2], a[1][3], b0, b1);
            }
        }
        __syncthreads();
        buf ^= 1;
    }

    #pragma unroll
    for (int mt = 0; mt < 2; mt++) {
        int rb = m0 + wm * 32 + mt * 16;
        #pragma unroll
        for (int nt = 0; nt < 8; nt++) {
            int n = n0 + wn * 64 + nt * 8 + 2 * t;
            epi(rb + g,     n, acc[mt][nt][0], acc[mt][nt][1]);
            epi(rb + g + 8, n, acc[mt][nt][2], acc[mt][nt][3]);
        }
    }
}

// ---------------------------------------------------------------------------
// Flash attention, tf32 mma. One CTA = 64 queries of one (b,h), 128 threads.
// 2-stage cp.async K/V double buffer; dedicated P buffer (also stages Q).
// QK B-fragments AND P/Q A-fragments via ldmatrix.x4 (K stored [j][d] =
// n-major, P/Q row-major -> both are native ldmatrix layouts for tf32).
// Dynamic smem: Ks[2][64][68] + Vs[2][64][72] + Ps[64][68]  (89088 B).
// ---------------------------------------------------------------------------
#define KS(b,r,c) Ks[(((b) << 6) + (r)) * 68 + (c)]
#define VS(b,r,c) Vs[(((b) << 6) + (r)) * 72 + (c)]
#define PS(r,c)   Ps[(r) * 68 + (c)]
#define ATTN_SMEM_BYTES ((2*64*68 + 2*64*72 + 64*68) * 4)

__global__ void __launch_bounds__(128, 2)
attn_tf32(const int* __restrict__ mask)
{
    extern __shared__ float smem[];
    float* Ks = smem;
    float* Vs = smem + 2 * 64 * 68;
    float* Ps = smem + 2 * 64 * 68 + 2 * 64 * 72;

    int tid  = threadIdx.x;
    int wid  = tid >> 5, lane = tid & 31;
    int g    = lane >> 2, t = lane & 3;
    int rr   = lane & 7, qq = lane >> 3;
    int qb   = wid * 16;
    int lrow = rr + ((qq & 1) << 3);          // A-frag lane row offset
    int lcol = (qq >> 1) << 2;                // A-frag lane col offset
    int brow = ((qq >> 1) << 3) + rr;         // B-frag-pair lane row offset
    int bcol = (qq & 1) << 2;                 // B-frag-pair lane col offset

    int bh = blockIdx.y;
    int q0 = blockIdx.x * 64;
    int bb = bh >> 3, hh = bh & 7;
    const float* Qb = g_q + (size_t)bh * S_ * DH_;
    const float* Kb = g_k + (size_t)bh * S_ * DH_;
    const float* Vb = g_v + (size_t)bh * S_ * DH_;
    const int* mrow = mask + bb * S_;

    auto load_stage = [&](int buf, int kt) {
        #pragma unroll
        for (int i = 0; i < 8; i++) {
            int idx = tid + i * 128;
            int r = idx >> 4, c = (idx & 15) * 4;
            cp_async16(&KS(buf, r, c), Kb + (size_t)(kt + r) * DH_ + c);
            cp_async16(&VS(buf, r, c), Vb + (size_t)(kt + r) * DH_ + c);
        }
    };

    // stage Q (prescaled) into Ps, grab register fragments
    #pragma unroll
    for (int i = 0; i < 8; i++) {
        int idx = tid + i * 128;
        int r = idx >> 4, c = (idx & 15) * 4;
        float4 v = *(const float4*)(Qb + (size_t)(q0 + r) * DH_ + c);
        const float sc = 0.125f;              // 1/sqrt(DH)
        *(float4*)&PS(r, c) = make_float4(v.x * sc, v.y * sc, v.z * sc, v.w * sc);
    }
    // start first K/V stage while Q settles
    load_stage(0, 0);
    CP_COMMIT();
    __syncthreads();

    uint32_t qa[8][4];
    #pragma unroll
    for (int ks = 0; ks < 8; ks++)
        ldsm_x4(qa[ks], &PS(qb + lrow, ks * 8 + lcol));

    float oacc[8][4];
    #pragma unroll
    for (int nt = 0; nt < 8; nt++)
        #pragma unroll
        for (int i = 0; i < 4; i++) oacc[nt][i] = 0.f;
    float mi[2] = { -INFINITY, -INFINITY };
    float li[2] = { 0.f, 0.f };

    int buf = 0;
    for (int kt = 0; kt < S_; kt += 64) {
        if (kt + 64 < S_) load_stage(buf ^ 1, kt + 64);
        CP_COMMIT();
        CP_WAIT1();
        __syncthreads();

        // S = Qs @ K^T
        float sacc[8][4];
        #pragma unroll
        for (int nt = 0; nt < 8; nt++)
            #pragma unroll
            for (int i = 0; i < 4; i++) sacc[nt][i] = 0.f;
        #pragma unroll
        for (int ks = 0; ks < 8; ks++) {
            int kk = ks * 8;
            #pragma unroll
            for (int ntp = 0; ntp < 4; ntp++) {
                uint32_t bfr[4];
                ldsm_x4(bfr, &KS(buf, ntp * 16 + brow, kk + bcol));
                mma_tf32(sacc[2*ntp],     qa[ks][0], qa[ks][1], qa[ks][2],
                         qa[ks][3], bfr[0], bfr[1]);
                mma_tf32(sacc[2*ntp + 1], qa[ks][0], qa[ks][1], qa[ks][2],
                         qa[ks][3], bfr[2], bfr[3]);
            }
        }

        // key-wise mask
        #pragma unroll
        for (int nt = 0; nt < 8; nt++) {
            int j = kt + nt * 8 + 2 * t;
            if (__ldg(mrow + j)     == 0) { sacc[nt][0] = -1e9f; sacc[nt][2] = -1e9f; }
            if (__ldg(mrow + j + 1) == 0) { sacc[nt][1] = -1e9f; sacc[nt][3] = -1e9f; }
        }

        // online softmax (rows g and g+8; stats shared across 4 t-lanes)
        #pragma unroll
        for (int h = 0; h < 2; h++) {
            float rm = -INFINITY;
            #pragma unroll
            for (int nt = 0; nt < 8; nt++)
                rm = fmaxf(rm, fmaxf(sacc[nt][2*h], sacc[nt][2*h + 1]));
            rm = fmaxf(rm, __shfl_xor_sync(0xffffffffu, rm, 1));
            rm = fmaxf(rm, __shfl_xor_sync(0xffffffffu, rm, 2));
            float mnew = fmaxf(mi[h], rm);
            float corr = __expf(mi[h] - mnew);
            mi[h] = mnew;
            float rs = 0.f;
            #pragma unroll
            for (int nt = 0; nt < 8; nt++) {
                float e0 = __expf(sacc[nt][2*h]     - mnew);
                float e1 = __expf(sacc[nt][2*h + 1] - mnew);
                sacc[nt][2*h]     = e0;
                sacc[nt][2*h + 1] = e1;
                rs += e0 + e1;
            }
            rs += __shfl_xor_sync(0xffffffffu, rs, 1);
            rs += __shfl_xor_sync(0xffffffffu, rs, 2);
            li[h] = li[h] * corr + rs;
            #pragma unroll
            for (int nt = 0; nt < 8; nt++) {
                oacc[nt][2*h]     *= corr;
                oacc[nt][2*h + 1] *= corr;
            }
        }

        // write P into Ps
        #pragma unroll
        for (int nt = 0; nt < 8; nt++) {
            int jc = nt * 8 + 2 * t;
            *(float2*)&PS(qb + g,     jc) = make_float2(sacc[nt][0], sacc[nt][1]);
            *(float2*)&PS(qb + g + 8, jc) = make_float2(sacc[nt][2], sacc[nt][3]);
        }
        __syncthreads();

        // O += P @ V
        #pragma unroll
        for (int js = 0; js < 8; js++) {
            int j0 = js * 8;
            uint32_t a[4];
            ldsm_x4(a, &PS(qb + lrow, j0 + lcol));
            #pragma unroll
            for (int nt = 0; nt < 8; nt++) {
                int db = nt * 8;
                uint32_t b0 = FBITS(VS(buf, j0 + t,     db + g));
                uint32_t b1 = FBITS(VS(buf, j0 + t + 4, db + g));
                mma_tf32(oacc[nt], a[0], a[1], a[2], a[3], b0, b1);
            }
        }
        __syncthreads();
        buf ^= 1;
    }

    // finalize: 1/l scale, write ctx in [B,S,E] layout
    #pragma unroll
    for (int h = 0; h < 2; h++) {
        float inv = 1.0f / li[h];
        int r = q0 + qb + g + 8 * h;
        float* orow = g_ctx + ((size_t)bb * S_ + r) * E_ + hh * DH_;
        #pragma unroll
        for (int nt = 0; nt < 8; nt++) {
            int d = nt * 8 + 2 * t;
            *(float2*)(orow + d) = make_float2(oacc[nt][2*h] * inv,
                                               oacc[nt][2*h + 1] * inv);
        }
    }
}

// ---------------------------------------------------------------------------
// kernel_launch: graph-capturable, no allocations
// ---------------------------------------------------------------------------
extern "C" void kernel_launch(void* const* d_in, const int* in_sizes, int n_in,
                              void* d_out, int out_size)
{
    const float* x    = (const float*)d_in[0];
    const int*   mask = (const int*)  d_in[1];
    const float* wq   = (const float*)d_in[2];
    const float* bq   = (const float*)d_in[3];
    const float* wk   = (const float*)d_in[4];
    const float* bk   = (const float*)d_in[5];
    const float* wv   = (const float*)d_in[6];
    const float* bv   = (const float*)d_in[7];
    const float* wo   = (const float*)d_in[8];
    const float* bo   = (const float*)d_in[9];
    const float* w1   = (const float*)d_in[10];
    const float* b1   = (const float*)d_in[11];
    const float* w2   = (const float*)d_in[12];
    const float* b2   = (const float*)d_in[13];
    const float* al1  = (const float*)d_in[14];
    const float* be1  = (const float*)d_in[15];
    const float* al2  = (const float*)d_in[16];
    const float* be2  = (const float*)d_in[17];
    float* out = (float*)d_out;

    // opt-in to >48KB dynamic smem (idempotent, not a stream op)
    cudaFuncSetAttribute(gemm_tf32<EpiQKV3>,
        cudaFuncAttributeMaxDynamicSharedMemorySize, GEMM_SMEM_BYTES);
    cudaFuncSetAttribute(gemm_tf32<EpiOProj>,
        cudaFuncAttributeMaxDynamicSharedMemorySize, GEMM_SMEM_BYTES);
    cudaFuncSetAttribute(gemm_tf32<EpiRelu>,
        cudaFuncAttributeMaxDynamicSharedMemorySize, GEMM_SMEM_BYTES);
    cudaFuncSetAttribute(gemm_tf32<EpiFinal>,
        cudaFuncAttributeMaxDynamicSharedMemorySize, GEMM_SMEM_BYTES);
    cudaFuncSetAttribute(attn_tf32,
        cudaFuncAttributeMaxDynamicSharedMemorySize, ATTN_SMEM_BYTES);

    // norm1
    ln_kernel<<<M_, 128>>>(x, al1, be1, 0);

    // Q/K/V projections merged into one launch (z selects weight)
    dim3 gqkv(E_ / 128, M_ / 128, 3);       // (4, 64, 3)
    gemm_tf32<EpiQKV3><<<gqkv, 256, GEMM_SMEM_BYTES>>>(
        0, wq, wk, wv, E_, E_, EpiQKV3{bq, bk, bv});

    // attention
    dim3 ga(S_ / 64, B_ * H_);              // (32, 32)
    attn_tf32<<<ga, 128, ATTN_SMEM_BYTES>>>(mask);

    // O projection + residual 1
    dim3 g512(E_ / 128, M_ / 128);          // (4, 64)
    gemm_tf32<EpiOProj><<<g512, 256, GEMM_SMEM_BYTES>>>(
        1, wo, wo, wo, E_, E_, EpiOProj{bo, x});

    // norm2
    ln_kernel<<<M_, 128>>>(nullptr, al2, be2, 1);

    // FFN1 (N=2048) with ReLU
    dim3 gff1(FF2 / 128, M_ / 128);         // (16, 64)
    gemm_tf32<EpiRelu><<<gff1, 256, GEMM_SMEM_BYTES>>>(
        2, w1, w1, w1, E_, FF2, EpiRelu{b1});

    // FFN2 (K=2048) + residual 2 -> final output
    gemm_tf32<EpiFinal><<<g512, 256, GEMM_SMEM_BYTES>>>(
        3, w2, w2, w2, FF2, E_, EpiFinal{out, b2});
}

// round 11
// speedup vs baseline: 6.5564x; 1.6659x over previous
#include <cuda_runtime.h>
#include <cuda_bf16.h>
#include <math.h>
#include <stdint.h>

// Problem dims (fixed by the reference)
#define B_   4
#define S_   2048
#define E_   512
#define H_   8
#define DH_  64
#define FF2  2048
#define M_   8192   // B_*S_

// ---------------------------------------------------------------------------
// Scratch buffers (device globals -- no allocations allowed)
// ---------------------------------------------------------------------------
static __device__ __nv_bfloat16 g_nb  [(size_t)M_ * E_];   // LN1 out
static __device__ __nv_bfloat16 g_qb  [(size_t)M_ * E_];   // [B,H,S,DH]
static __device__ __nv_bfloat16 g_kb  [(size_t)M_ * E_];
static __device__ __nv_bfloat16 g_vb  [(size_t)M_ * E_];
static __device__ __nv_bfloat16 g_ctxb[(size_t)M_ * E_];   // attn out [B,S,E]
static __device__ __nv_bfloat16 g_n2b [(size_t)M_ * E_];   // LN2 out
static __device__ __nv_bfloat16 g_hb  [(size_t)M_ * FF2];  // FFN hidden
static __device__ float         g_x1  [(size_t)M_ * E_];   // residual-1 (fp32)
// transposed bf16 weights, layout [N][K]
static __device__ __nv_bfloat16 g_wtq[E_ * E_];
static __device__ __nv_bfloat16 g_wtk[E_ * E_];
static __device__ __nv_bfloat16 g_wtv[E_ * E_];
static __device__ __nv_bfloat16 g_wto[E_ * E_];
static __device__ __nv_bfloat16 g_wt1[(size_t)FF2 * E_];   // [2048][512]
static __device__ __nv_bfloat16 g_wt2[(size_t)E_ * FF2];   // [512][2048]

// ---------------------------------------------------------------------------
// PTX helpers (family-portable only: cp.async, ldmatrix, mma.sync)
// ---------------------------------------------------------------------------
__device__ __forceinline__ uint32_t smem_u32(const void* p) {
    return (uint32_t)__cvta_generic_to_shared(p);
}
__device__ __forceinline__ void cp_async16_s(uint32_t saddr, const void* g) {
    asm volatile("cp.async.cg.shared.global [%0], [%1], 16;"
                 :: "r"(saddr), "l"(g));
}
#define CP_COMMIT() asm volatile("cp.async.commit_group;" ::: "memory")
#define CP_WAIT0()  asm volatile("cp.async.wait_group 0;" ::: "memory")
#define CP_WAIT1()  asm volatile("cp.async.wait_group 1;" ::: "memory")
#define CP_WAIT2()  asm volatile("cp.async.wait_group 2;" ::: "memory")

// bf16 m16n8k16 mma.sync
__device__ __forceinline__ void mma_bf16(float c[4], const uint32_t a[4],
                                         uint32_t b0, uint32_t b1)
{
    asm volatile(
        "mma.sync.aligned.m16n8k16.row.col.f32.bf16.bf16.f32 "
        "{%0,%1,%2,%3}, {%4,%5,%6,%7}, {%8,%9}, {%0,%1,%2,%3};"
        : "+f"(c[0]), "+f"(c[1]), "+f"(c[2]), "+f"(c[3])
        : "r"(a[0]), "r"(a[1]), "r"(a[2]), "r"(a[3]), "r"(b0), "r"(b1));
}
__device__ __forceinline__ void ldsm_x4_u(uint32_t r[4], uint32_t saddr) {
    asm volatile("ldmatrix.sync.aligned.m8n8.x4.shared.b16 {%0,%1,%2,%3}, [%4];"
        : "=r"(r[0]), "=r"(r[1]), "=r"(r[2]), "=r"(r[3]) : "r"(saddr));
}
__device__ __forceinline__ void ldsm_x4(uint32_t r[4], const void* p) {
    ldsm_x4_u(r, smem_u32(p));
}
__device__ __forceinline__ void ldsm_x4_t(uint32_t r[4], const void* p) {
    uint32_t s = smem_u32(p);
    asm volatile("ldmatrix.sync.aligned.m8n8.x4.trans.shared.b16 {%0,%1,%2,%3}, [%4];"
        : "=r"(r[0]), "=r"(r[1]), "=r"(r[2]), "=r"(r[3]) : "r"(s));
}

// ---------------------------------------------------------------------------
// Weight transpose + bf16 convert: in fp32 [K,N] -> out bf16 [N,K]
// ---------------------------------------------------------------------------
__global__ void wtrans_kernel(const float* __restrict__ in, int K, int N, int wsel)
{
    __nv_bfloat16* out = (wsel == 0) ? g_wtq : (wsel == 1) ? g_wtk
                       : (wsel == 2) ? g_wtv : (wsel == 3) ? g_wto
                       : (wsel == 4) ? g_wt1 : g_wt2;
    __shared__ float t[32][33];
    int bx = blockIdx.x * 32, by = blockIdx.y * 32;
    int tx = threadIdx.x, ty = threadIdx.y;          // 32 x 8
    #pragma unroll
    for (int j = 0; j < 32; j += 8)
        t[ty + j][tx] = in[(size_t)(by + ty + j) * N + bx + tx];
    __syncthreads();
    #pragma unroll
    for (int j = 0; j < 32; j += 8)
        out[(size_t)(bx + ty + j) * K + by + tx] = __float2bfloat16(t[tx][ty + j]);
}

// ---------------------------------------------------------------------------
// LayerNorm (mean + unbiased std ddof=1, eps on std) -> bf16 output
// ---------------------------------------------------------------------------
__global__ void ln_kernel(const float* __restrict__ xext,
                          const float* __restrict__ alpha,
                          const float* __restrict__ beta, int which)
{
    const float* x      = (which == 0) ? xext : g_x1;
    __nv_bfloat16* out  = (which == 0) ? g_nb : g_n2b;
    int row = blockIdx.x;
    int t   = threadIdx.x;
    float4 v = ((const float4*)(x + (size_t)row * E_))[t];
    float s  = v.x + v.y + v.z + v.w;
    float sq = v.x*v.x + v.y*v.y + v.z*v.z + v.w*v.w;
    #pragma unroll
    for (int o = 16; o; o >>= 1) {
        s  += __shfl_xor_sync(0xffffffffu, s,  o);
        sq += __shfl_xor_sync(0xffffffffu, sq, o);
    }
    __shared__ float ss[4], sqs[4];
    int w = t >> 5;
    if ((t & 31) == 0) { ss[w] = s; sqs[w] = sq; }
    __syncthreads();
    s  = ss[0] + ss[1] + ss[2] + ss[3];
    sq = sqs[0] + sqs[1] + sqs[2] + sqs[3];
    float mean = s * (1.0f / E_);
    float var  = fmaxf((sq - (float)E_ * mean * mean) * (1.0f / (E_ - 1)), 0.0f);
    float scal = alpha[0] / (sqrtf(var) + 1e-6f);
    float b    = beta[0];
    __nv_bfloat162 o0 = __floats2bfloat162_rn((v.x - mean) * scal + b,
                                              (v.y - mean) * scal + b);
    __nv_bfloat162 o1 = __floats2bfloat162_rn((v.z - mean) * scal + b,
                                              (v.w - mean) * scal + b);
    uint2 pk = make_uint2(*(uint32_t*)&o0, *(uint32_t*)&o1);
    ((uint2*)(out + (size_t)row * E_))[t] = pk;
}

// ---------------------------------------------------------------------------
// Epilogue functors: (m, n, v0, v1) = two adjacent-n fp32 accumulator values
// ---------------------------------------------------------------------------
struct EpiQKV3 {                // z selects q/k/v; bf16 out in [B,H,S,DH]
    const float *bq, *bk, *bv;
    __device__ __forceinline__ void operator()(int m, int n, float v0, float v1) const {
        int z = blockIdx.z;
        const float* bias  = (z == 0) ? bq : (z == 1) ? bk : bv;
        __nv_bfloat16* out = (z == 0) ? g_qb : (z == 1) ? g_kb : g_vb;
        int b = m >> 11, s = m & (S_ - 1);
        int h = n >> 6,  d = n & 63;
        __nv_bfloat162 o = __floats2bfloat162_rn(v0 + bias[n], v1 + bias[n + 1]);
        *(__nv_bfloat162*)(out + ((((size_t)b * H_ + h) * S_ + s) * DH_ + d)) = o;
    }
};
struct EpiOProj {               // g_x1 = x + ctx@wo + bo   (fp32)
    const float* bias; const float* resid;
    __device__ __forceinline__ void operator()(int m, int n, float v0, float v1) const {
        size_t idx = (size_t)m * E_ + n;
        float2 r = *(const float2*)(resid + idx);
        *(float2*)(g_x1 + idx) =
            make_float2(v0 + bias[n] + r.x, v1 + bias[n + 1] + r.y);
    }
};
struct EpiRelu {                // g_hb = relu(n2@w1 + b1)  (bf16)
    const float* bias;
    __device__ __forceinline__ void operator()(int m, int n, float v0, float v1) const {
        __nv_bfloat162 o = __floats2bfloat162_rn(fmaxf(v0 + bias[n],     0.f),
                                                 fmaxf(v1 + bias[n + 1], 0.f));
        *(__nv_bfloat162*)(g_hb + (size_t)m * FF2 + n) = o;
    }
};
struct EpiFinal {               // out = x1 + h@w2 + b2     (fp32)
    float* out; const float* bias;
    __device__ __forceinline__ void operator()(int m, int n, float v0, float v1) const {
        size_t idx = (size_t)m * E_ + n;
        float2 r = *(const float2*)(g_x1 + idx);
        *(float2*)(out + idx) =
            make_float2(v0 + bias[n] + r.x, v1 + bias[n + 1] + r.y);
    }
};

__device__ __forceinline__ const __nv_bfloat16* gemm_A(int s) {
    return (s == 0) ? g_nb : (s == 1) ? g_ctxb : (s == 2) ? g_n2b : g_hb;
}
__device__ __forceinline__ const __nv_bfloat16* gemm_W(int s) {
    return (s == 0) ? g_wtq : (s == 1) ? g_wtk : (s == 2) ? g_wtv
         : (s == 3) ? g_wto : (s == 4) ? g_wt1 : g_wt2;
}

// ---------------------------------------------------------------------------
// bf16 mma.sync GEMM: C[M,N] = A[M,K] @ Wt[N,K]^T  (+ epilogue)
// CTA tile 128x128, BK=32, 256 threads = 8 warps (4m x 2n), warp tile 32x64.
// 4-stage cp.async pipeline. All fragments via ldmatrix.x4.
// smem per stage: A 128 rows x 80 B + B 128 rows x 80 B (stride 80 B: bank
// group (5r+g) mod 8 is a permutation over 8 rows -> ldmatrix conflict-free).
// ---------------------------------------------------------------------------
#define G_ROWB       80
#define GA_BYTES     (128 * G_ROWB)          // 10240
#define GSTAGE_BYTES (2 * GA_BYTES)          // 20480
#define GT_SMEM      (4 * GSTAGE_BYTES)      // 81920

template <class Epi>
__global__ void __launch_bounds__(256, 2)
gemm_bf16(int asel, int wsel0, int K, int N, Epi epi)
{
    extern __shared__ char smem[];
    uint32_t sb = smem_u32(smem);
    const __nv_bfloat16* A = gemm_A(asel);
    const __nv_bfloat16* W = gemm_W(wsel0 + blockIdx.z);
    int m0 = blockIdx.y * 128, n0 = blockIdx.x * 128;
    int tid = threadIdx.x, wid = tid >> 5, lane = tid & 31;
    int g = lane >> 2, t = lane & 3;
    int wm = wid & 3, wn = wid >> 2;
    // ldmatrix lane offsets
    int arow = lane & 15;                        // A: rows 0..15
    int acol = (lane >> 4) << 3;                 // A: k halves
    int brow = ((lane >> 4) << 3) + (lane & 7);  // B: n offset 0..15
    int bcol = ((lane >> 3) & 1) << 3;           // B: k halves

    const __nv_bfloat16* Ab = A + (size_t)m0 * K;
    const __nv_bfloat16* Wb = W + (size_t)n0 * K;
    const int NC = K >> 5;                       // BK=32 chunks

    auto load_chunk = [&](int ci) {
        uint32_t base = sb + (ci & 3) * GSTAGE_BYTES;
        const __nv_bfloat16* Ap = Ab + ci * 32;
        const __nv_bfloat16* Wp = Wb + ci * 32;
        #pragma unroll
        for (int i = 0; i < 2; i++) {            // 512 rows*4 groups / 256 thr
            int idx = tid + i * 256;
            int r = idx >> 2, cg = idx & 3;
            cp_async16_s(base + r * G_ROWB + cg * 16,
                         Ap + (size_t)r * K + cg * 8);
            cp_async16_s(base + GA_BYTES + r * G_ROWB + cg * 16,
                         Wp + (size_t)r * K + cg * 8);
        }
    };

    float acc[2][8][4];
    #pragma unroll
    for (int mt = 0; mt < 2; mt++)
        #pragma unroll
        for (int nt = 0; nt < 8; nt++)
            #pragma unroll
            for (int i = 0; i < 4; i++) acc[mt][nt][i] = 0.f;

    load_chunk(0); CP_COMMIT();
    load_chunk(1); CP_COMMIT();
    load_chunk(2); CP_COMMIT();

    for (int i = 0; i < NC; i++) {
        if (i + 2 < NC)      CP_WAIT2();
        else if (i + 1 < NC) CP_WAIT1();
        else                 CP_WAIT0();
        __syncthreads();                 // chunk i visible; buf (i-1)%4 free
        if (i + 3 < NC) { load_chunk(i + 3); CP_COMMIT(); }

        uint32_t abase = sb + (i & 3) * GSTAGE_BYTES;
        uint32_t bbase = abase + GA_BYTES;
        #pragma unroll
        for (int ks = 0; ks < 2; ks++) {
            int kk = ks * 16;
            uint32_t a[2][4];
            #pragma unroll
            for (int mt = 0; mt < 2; mt++)
                ldsm_x4_u(a[mt], abase + (wm * 32 + mt * 16 + arow) * G_ROWB
                                        + (kk + acol) * 2);
            #pragma unroll
            for (int np = 0; np < 4; np++) {
                uint32_t bfr[4];
                ldsm_x4_u(bfr, bbase + (wn * 64 + np * 16 + brow) * G_ROWB
                                      + (kk + bcol) * 2);
                #pragma unroll
                for (int mt = 0; mt < 2; mt++) {
                    mma_bf16(acc[mt][2*np],     a[mt], bfr[0], bfr[1]);
                    mma_bf16(acc[mt][2*np + 1], a[mt], bfr[2], bfr[3]);
                }
            }
        }
    }

    #pragma unroll
    for (int mt = 0; mt < 2; mt++) {
        int rb = m0 + wm * 32 + mt * 16;
        #pragma unroll
        for (int nt = 0; nt < 8; nt++) {
            int n = n0 + wn * 64 + nt * 8 + 2 * t;
            epi(rb + g,     n, acc[mt][nt][0], acc[mt][nt][1]);
            epi(rb + g + 8, n, acc[mt][nt][2], acc[mt][nt][3]);
        }
    }
}

// ---------------------------------------------------------------------------
// Flash attention, bf16 m16n8k16 mma.sync. One CTA = 64 queries of one (b,h),
// 128 threads (4 warps, warp w owns q rows 16w..16w+15).
// smem (bf16, row stride 144 B): Ks[2][64], Vs[2][64], Ps[64] (Q then P)
// ---------------------------------------------------------------------------
#define KSP(b,r) ((__nv_bfloat16*)(smem + ((b) * 64 + (r)) * 144))
#define VSP(b,r) ((__nv_bfloat16*)(smem + 18432 + ((b) * 64 + (r)) * 144))
#define PSP(r)   ((__nv_bfloat16*)(smem + 36864 + (r) * 144))
#define ATTN_SMEM_BYTES (36864 + 9216)

__global__ void __launch_bounds__(128, 4)
attn_bf16(const int* __restrict__ mask)
{
    extern __shared__ char smem[];
    uint32_t sb = smem_u32(smem);

    int tid  = threadIdx.x;
    int wid  = tid >> 5, lane = tid & 31;
    int g    = lane >> 2, t = lane & 3;
    int qb   = wid * 16;
    // ldmatrix lane offsets
    int arow = lane & 15;                  // A frag row
    int acol = (lane >> 4) << 3;           // A frag col (elems)
    int kbr  = ((lane >> 4) << 3) + (lane & 7);        // K B-frag: n offset
    int kbc  = ((lane >> 3) & 1) << 3;                 // K B-frag: k offset
    int vbr  = (((lane >> 3) & 1) << 3) + (lane & 7);  // V trans: j offset
    int vbc  = (lane >> 4) << 3;                       // V trans: d offset

    int bh = blockIdx.y;
    int q0 = blockIdx.x * 64;
    int bb = bh >> 3, hh = bh & 7;
    const __nv_bfloat16* Qb = g_qb + (size_t)bh * S_ * DH_;
    const __nv_bfloat16* Kb = g_kb + (size_t)bh * S_ * DH_;
    const __nv_bfloat16* Vb = g_vb + (size_t)bh * S_ * DH_;
    const int* mrow = mask + bb * S_;

    auto load_kv = [&](int ci) {
        int buf = ci & 1;
        #pragma unroll
        for (int i = 0; i < 4; i++) {               // 512 chunks / 128 thr
            int idx = tid + i * 128;
            int r = idx >> 3, cB = (idx & 7) << 4;
            cp_async16_s(sb + (buf * 64 + r) * 144 + cB,
                         Kb + (size_t)(ci * 64 + r) * DH_ + (cB >> 1));
            cp_async16_s(sb + 18432 + (buf * 64 + r) * 144 + cB,
                         Vb + (size_t)(ci * 64 + r) * DH_ + (cB >> 1));
        }
    };

    // stage Q into Ps
    #pragma unroll
    for (int i = 0; i < 4; i++) {
        int idx = tid + i * 128;
        int r = idx >> 3, cB = (idx & 7) << 4;
        cp_async16_s(sb + 36864 + r * 144 + cB,
                     Qb + (size_t)(q0 + r) * DH_ + (cB >> 1));
    }
    CP_COMMIT();
    load_kv(0); CP_COMMIT();
    load_kv(1); CP_COMMIT();

    CP_WAIT2();                 // Q resident
    __syncthreads();
    uint32_t qa[4][4];
    #pragma unroll
    for (int ks = 0; ks < 4; ks++)
        ldsm_x4(qa[ks], PSP(qb + arow) + ks * 16 + acol);

    float oacc[8][4];
    #pragma unroll
    for (int nt = 0; nt < 8; nt++)
        #pragma unroll
        for (int i = 0; i < 4; i++) oacc[nt][i] = 0.f;
    float mi[2] = { -INFINITY, -INFINITY };
    float li[2] = { 0.f, 0.f };

    const int NC = S_ / 64;
    for (int i = 0; i < NC; i++) {
        if (i + 1 < NC) CP_WAIT1(); else CP_WAIT0();
        __syncthreads();
        int buf = i & 1;
        int kt  = i * 64;

        // S = Q @ K^T  (K tile [j][d] = n-major -> native B frags)
        float sacc[8][4];
        #pragma unroll
        for (int nt = 0; nt < 8; nt++)
            #pragma unroll
            for (int j = 0; j < 4; j++) sacc[nt][j] = 0.f;
        #pragma unroll
        for (int ks = 0; ks < 4; ks++) {
            int kk = ks * 16;
            #pragma unroll
            for (int np = 0; np < 4; np++) {
                uint32_t bfr[4];
                ldsm_x4(bfr, KSP(buf, np * 16 + kbr) + kk + kbc);
                mma_bf16(sacc[2*np],     qa[ks], bfr[0], bfr[1]);
                mma_bf16(sacc[2*np + 1], qa[ks], bfr[2], bfr[3]);
            }
        }

        // scale, mask
        #pragma unroll
        for (int nt = 0; nt < 8; nt++) {
            #pragma unroll
            for (int j = 0; j < 4; j++) sacc[nt][j] *= 0.125f;
            int jg = kt + nt * 8 + 2 * t;
            if (__ldg(mrow + jg)     == 0) { sacc[nt][0] = -1e9f; sacc[nt][2] = -1e9f; }
            if (__ldg(mrow + jg + 1) == 0) { sacc[nt][1] = -1e9f; sacc[nt][3] = -1e9f; }
        }

        // online softmax (rows g, g+8; stats shared across 4 t-lanes)
        #pragma unroll
        for (int h = 0; h < 2; h++) {
            float rm = -INFINITY;
            #pragma unroll
            for (int nt = 0; nt < 8; nt++)
                rm = fmaxf(rm, fmaxf(sacc[nt][2*h], sacc[nt][2*h + 1]));
            rm = fmaxf(rm, __shfl_xor_sync(0xffffffffu, rm, 1));
            rm = fmaxf(rm, __shfl_xor_sync(0xffffffffu, rm, 2));
            float mnew = fmaxf(mi[h], rm);
            float corr = __expf(mi[h] - mnew);
            mi[h] = mnew;
            float rs = 0.f;
            #pragma unroll
            for (int nt = 0; nt < 8; nt++) {
                float e0 = __expf(sacc[nt][2*h]     - mnew);
                float e1 = __expf(sacc[nt][2*h + 1] - mnew);
                sacc[nt][2*h]     = e0;
                sacc[nt][2*h + 1] = e1;
                rs += e0 + e1;
            }
            rs += __shfl_xor_sync(0xffffffffu, rs, 1);
            rs += __shfl_xor_sync(0xffffffffu, rs, 2);
            li[h] = li[h] * corr + rs;
            #pragma unroll
            for (int nt = 0; nt < 8; nt++) {
                oacc[nt][2*h]     *= corr;
                oacc[nt][2*h + 1] *= corr;
            }
        }

        // P -> smem (bf16). Each warp only touches its own 16 rows.
        #pragma unroll
        for (int nt = 0; nt < 8; nt++) {
            int jc = nt * 8 + 2 * t;
            *(__nv_bfloat162*)(PSP(qb + g)     + jc) =
                __floats2bfloat162_rn(sacc[nt][0], sacc[nt][1]);
            *(__nv_bfloat162*)(PSP(qb + g + 8) + jc) =
                __floats2bfloat162_rn(sacc[nt][2], sacc[nt][3]);
        }
        __syncwarp();

        // O += P @ V  (V tile [j][d] -> trans ldsm gives [d][j] B frags)
        #pragma unroll
        for (int js = 0; js < 4; js++) {
            int j0 = js * 16;
            uint32_t a[4];
            ldsm_x4(a, PSP(qb + arow) + j0 + acol);
            #pragma unroll
            for (int np = 0; np < 4; np++) {
                uint32_t bfr[4];
                ldsm_x4_t(bfr, VSP(buf, j0 + vbr) + np * 16 + vbc);
                mma_bf16(oacc[2*np],     a, bfr[0], bfr[1]);
                mma_bf16(oacc[2*np + 1], a, bfr[2], bfr[3]);
            }
        }
        __syncthreads();
        if (i + 2 < NC) { load_kv(i + 2); CP_COMMIT(); }
    }

    // finalize: 1/l, write bf16 ctx in [B,S,E] layout
    #pragma unroll
    for (int h = 0; h < 2; h++) {
        float inv = 1.0f / li[h];
        int r = q0 + qb + g + 8 * h;
        __nv_bfloat16* orow = g_ctxb + ((size_t)bb * S_ + r) * E_ + hh * DH_;
        #pragma unroll
        for (int nt = 0; nt < 8; nt++) {
            int d = nt * 8 + 2 * t;
            *(__nv_bfloat162*)(orow + d) =
                __floats2bfloat162_rn(oacc[nt][2*h] * inv, oacc[nt][2*h + 1] * inv);
        }
    }
}

// ---------------------------------------------------------------------------
// kernel_launch: graph-capturable, no allocations
// ---------------------------------------------------------------------------
extern "C" void kernel_launch(void* const* d_in, const int* in_sizes, int n_in,
                              void* d_out, int out_size)
{
    const float* x    = (const float*)d_in[0];
    const int*   mask = (const int*)  d_in[1];
    const float* wq   = (const float*)d_in[2];
    const float* bq   = (const float*)d_in[3];
    const float* wk   = (const float*)d_in[4];
    const float* bk   = (const float*)d_in[5];
    const float* wv   = (const float*)d_in[6];
    const float* bv   = (const float*)d_in[7];
    const float* wo   = (const float*)d_in[8];
    const float* bo   = (const float*)d_in[9];
    const float* w1   = (const float*)d_in[10];
    const float* b1   = (const float*)d_in[11];
    const float* w2   = (const float*)d_in[12];
    const float* b2   = (const float*)d_in[13];
    const float* al1  = (const float*)d_in[14];
    const float* be1  = (const float*)d_in[15];
    const float* al2  = (const float*)d_in[16];
    const float* be2  = (const float*)d_in[17];
    float* out = (float*)d_out;

    cudaFuncSetAttribute(gemm_bf16<EpiQKV3>,
        cudaFuncAttributeMaxDynamicSharedMemorySize, GT_SMEM);
    cudaFuncSetAttribute(gemm_bf16<EpiOProj>,
        cudaFuncAttributeMaxDynamicSharedMemorySize, GT_SMEM);
    cudaFuncSetAttribute(gemm_bf16<EpiRelu>,
        cudaFuncAttributeMaxDynamicSharedMemorySize, GT_SMEM);
    cudaFuncSetAttribute(gemm_bf16<EpiFinal>,
        cudaFuncAttributeMaxDynamicSharedMemorySize, GT_SMEM);
    cudaFuncSetAttribute(attn_bf16,
        cudaFuncAttributeMaxDynamicSharedMemorySize, ATTN_SMEM_BYTES);

    dim3 tb(32, 8);
    // weight transpose + bf16 convert ([K,N] -> [N,K])
    wtrans_kernel<<<dim3(E_/32,  E_/32),  tb>>>(wq, E_,  E_,  0);
    wtrans_kernel<<<dim3(E_/32,  E_/32),  tb>>>(wk, E_,  E_,  1);
    wtrans_kernel<<<dim3(E_/32,  E_/32),  tb>>>(wv, E_,  E_,  2);
    wtrans_kernel<<<dim3(E_/32,  E_/32),  tb>>>(wo, E_,  E_,  3);
    wtrans_kernel<<<dim3(FF2/32, E_/32),  tb>>>(w1, E_,  FF2, 4);
    wtrans_kernel<<<dim3(E_/32,  FF2/32), tb>>>(w2, FF2, E_,  5);

    // norm1
    ln_kernel<<<M_, 128>>>(x, al1, be1, 0);

    // Q/K/V projections (one launch, z selects weight/out)
    dim3 gqkv(E_ / 128, M_ / 128, 3);
    gemm_bf16<EpiQKV3><<<gqkv, 256, GT_SMEM>>>(
        0, 0, E_, E_, EpiQKV3{bq, bk, bv});

    // attention
    dim3 ga(S_ / 64, B_ * H_);
    attn_bf16<<<ga, 128, ATTN_SMEM_BYTES>>>(mask);

    // O projection + residual 1
    dim3 g512(E_ / 128, M_ / 128, 1);
    gemm_bf16<EpiOProj><<<g512, 256, GT_SMEM>>>(
        1, 3, E_, E_, EpiOProj{bo, x});

    // norm2
    ln_kernel<<<M_, 128>>>(nullptr, al2, be2, 1);

    // FFN1 (N=2048) with ReLU
    dim3 gff1(FF2 / 128, M_ / 128, 1);
    gemm_bf16<EpiRelu><<<gff1, 256, GT_SMEM>>>(
        2, 4, E_, FF2, EpiRelu{b1});

    // FFN2 (K=2048) + residual 2 -> final output
    gemm_bf16<EpiFinal><<<g512, 256, GT_SMEM>>>(
        3, 5, FF2, E_, EpiFinal{out, b2});
}